// round 3
// baseline (speedup 1.0000x reference)
#include <cuda_runtime.h>

// x [32, 512, 512] f32 -> pad 128 -> [32,768,768] -> NN upsample x4 -> [32,3072,3072] f32.
// out[b, i, j] = x[b, i/4 - 128, j/4 - 128] if in-bounds else 0.
//
// One thread = 4 output rows x 2 float4 cols (col pair split 384 groups apart
// so each STG.128 is perfectly warp-coalesced):
//   2 LDG.32 (L2-resident; input = 32MB << 126MB L2)
//   8 STG.128 evict-first, batched for store-queue depth.
// DRAM traffic = 1.21 GB stores (minimum).

#define B        32
#define HW       512
#define OW       3072         // (512 + 2*128) * 4
#define OW4      768          // float4 groups per output row
#define HALF     384          // col-pair stride in float4 groups
#define SRCROWS  768          // padded source rows (= output rows / 4)
#define TILES_PER_B (SRCROWS * HALF)      // 294912 tiles per batch image
#define NTILES   (B * TILES_PER_B)        // 9437184 total tiles

__global__ __launch_bounds__(256) void scale_layer_kernel(
    const float* __restrict__ x, float4* __restrict__ out)
{
    unsigned idx = blockIdx.x * 256u + threadIdx.x;

    unsigned b     = idx / (unsigned)TILES_PER_B;
    unsigned rem   = idx - b * (unsigned)TILES_PER_B;
    unsigned orow4 = rem / (unsigned)HALF;        // padded source row [0,768)
    unsigned oq    = rem - orow4 * (unsigned)HALF; // first col group [0,384)

    int r  = (int)orow4 - 128;          // source row
    int c0 = (int)oq - 128;             // source col for first group
    int c1 = (int)oq + (HALF - 128);    // source col for second group (= c0+384)

    const float* row = x + (size_t)b * (HW * HW) + (unsigned)r * HW;

    float v0 = 0.0f, v1 = 0.0f;
    bool rok = (unsigned)r < (unsigned)HW;
    if (rok && (unsigned)c0 < (unsigned)HW) v0 = __ldg(row + (unsigned)c0);
    if (rok && (unsigned)c1 < (unsigned)HW) v1 = __ldg(row + (unsigned)c1);

    float4 a = make_float4(v0, v0, v0, v0);
    float4 d = make_float4(v1, v1, v1, v1);

    // Output base: row orow4*4 of batch b, float4 column oq.
    float4* p = out + ((size_t)b * OW + (size_t)orow4 * 4u) * OW4 + oq;
    __stcs(p,                  a);
    __stcs(p + HALF,           d);
    __stcs(p + OW4,            a);
    __stcs(p + OW4 + HALF,     d);
    __stcs(p + 2 * OW4,        a);
    __stcs(p + 2 * OW4 + HALF, d);
    __stcs(p + 3 * OW4,        a);
    __stcs(p + 3 * OW4 + HALF, d);
}

extern "C" void kernel_launch(void* const* d_in, const int* in_sizes, int n_in,
                              void* d_out, int out_size)
{
    const float* x = (const float*)d_in[0];
    float4* out = (float4*)d_out;
    // NTILES / 256 = 36864 blocks exactly
    scale_layer_kernel<<<NTILES / 256, 256>>>(x, out);
}

// round 4
// speedup vs baseline: 1.0021x; 1.0021x over previous
#include <cuda_runtime.h>

// x [32, 512, 512] f32 -> pad 128 -> [32,768,768] -> NN upsample x4 -> [32,3072,3072] f32.
// out[b, i, j] = x[b, i/4 - 128, j/4 - 128] if in-bounds else 0.
//
// One thread = one 8-float (32B) output group x 4 output rows.
// The 8 output floats cover two adjacent source cols (2g-128, 2g-127),
// the 4 rows share one source row:
//   1 LDG.64 (L2-resident input) + 4 STG.256 (st.global.cs.v8.f32, sm_100a+).
// Each warp store = 1024B contiguous. DRAM traffic = 1.21 GB stores (minimum).

#define B        32
#define HW       512
#define OW       3072         // (512 + 2*128) * 4
#define OW4      768          // float4 groups per output row
#define GRP      384          // v8 (32B) groups per output row
#define SRCROWS  768          // padded source rows
#define TILES_PER_B (SRCROWS * GRP)       // 294912
#define NTILES   (B * TILES_PER_B)        // 9437184

__device__ __forceinline__ void st256_cs(float4* p, float a, float b) {
    asm volatile(
        "st.global.cs.v8.f32 [%0], {%1,%2,%3,%4,%5,%6,%7,%8};"
        :: "l"(p), "f"(a), "f"(a), "f"(a), "f"(a),
           "f"(b), "f"(b), "f"(b), "f"(b)
        : "memory");
}

__global__ __launch_bounds__(256) void scale_layer_kernel(
    const float* __restrict__ x, float4* __restrict__ out)
{
    unsigned idx = blockIdx.x * 256u + threadIdx.x;

    unsigned b     = idx / (unsigned)TILES_PER_B;
    unsigned rem   = idx - b * (unsigned)TILES_PER_B;
    unsigned orow4 = rem / (unsigned)GRP;          // padded source row [0,768)
    unsigned g     = rem - orow4 * (unsigned)GRP;  // v8 col group [0,384)

    int r = (int)orow4 - 128;        // source row
    int c = (int)(g * 2u) - 128;     // first of two source cols (always even)

    float v0 = 0.0f, v1 = 0.0f;
    if ((unsigned)r < (unsigned)HW && (unsigned)c < (unsigned)HW) {
        // c in-bounds implies c+1 in-bounds (c even, HW even)
        float2 s = *(const float2*)(x + (size_t)b * (HW * HW)
                                      + (unsigned)r * HW + (unsigned)c);
        v0 = s.x; v1 = s.y;
    }

    // Output base: row orow4*4, float4 column 2g (even -> 32B aligned).
    float4* p = out + ((size_t)b * OW + (size_t)orow4 * 4u) * OW4 + 2u * g;
    st256_cs(p,           v0, v1);
    st256_cs(p + OW4,     v0, v1);
    st256_cs(p + 2 * OW4, v0, v1);
    st256_cs(p + 3 * OW4, v0, v1);
}

extern "C" void kernel_launch(void* const* d_in, const int* in_sizes, int n_in,
                              void* d_out, int out_size)
{
    const float* x = (const float*)d_in[0];
    float4* out = (float4*)d_out;
    // NTILES / 256 = 36864 blocks exactly
    scale_layer_kernel<<<NTILES / 256, 256>>>(x, out);
}